// round 7
// baseline (speedup 1.0000x reference)
#include <cuda_runtime.h>

// SSIM loss: 1 - mean(ssim_map(clip(denoised), clip(clean)))
// Separable 11x11 Gaussian (sigma=1.5), zero padding.
// (32,3,512,512) fp32 x2 -> scalar fp32.
// Group-of-8 reuse in both conv passes; FFMA-imm weights; 256 thr, 3 blocks/SM.

#define IMGW 512
#define IMGH 512
#define TW 32
#define TH 64
#define HALO 5
#define RAWV 74          // TH + 2*HALO
#define RAWH 42          // TW + 2*HALO
#define RS 45            // odd row stride (float2 units) for raw tile
#define HS 32            // hsum row stride
#define NPIX 25165824.0  // 32*3*512*512
#define NBLK (16*8*96)   // 12288

__device__ float g_part[NBLK];

// dynamic smem layout:
//  s_ab : float2[RAWV*RS] = 26640 B
//  s_hm : float2[RAWV*HS] = 18944 B   (mu1, mu2 h-conv)
//  s_hq : float2[RAWV*HS] = 18944 B   (E11, E22 h-conv)
//  s_h12: float [RAWV*HS] =  9472 B   (E12 h-conv)
#define OFF_AB   0
#define OFF_HM   (OFF_AB + RAWV*RS*8)
#define OFF_HQ   (OFF_HM + RAWV*HS*8)
#define OFF_H12  (OFF_HQ + RAWV*HS*8)
#define SMEM_TOT (OFF_H12 + RAWV*HS*4)

__global__ __launch_bounds__(256, 3) void ssim_main_kernel(
    const float* __restrict__ in1, const float* __restrict__ in2) {

    const float W[11] = {
        0.00102838f, 0.00759876f, 0.03600077f, 0.10936073f, 0.21300554f,
        0.26601172f,
        0.21300554f, 0.10936073f, 0.03600077f, 0.00759876f, 0.00102838f
    };

    extern __shared__ char smem[];
    float2* s_ab  = reinterpret_cast<float2*>(smem + OFF_AB);
    float2* s_hm  = reinterpret_cast<float2*>(smem + OFF_HM);
    float2* s_hq  = reinterpret_cast<float2*>(smem + OFF_HQ);
    float*  s_h12 = reinterpret_cast<float*>(smem + OFF_H12);
    __shared__ float wsum[8];

    const int tid = threadIdx.x;
    const int plane = blockIdx.z;
    const int row0 = blockIdx.y * TH;
    const int col0 = blockIdx.x * TW;
    const float* p1 = in1 + (size_t)plane * (IMGW * IMGH);
    const float* p2 = in2 + (size_t)plane * (IMGW * IMGH);

    // ---- Load + clip raw tile with halo (zero outside image) ----
    for (int idx = tid; idx < RAWV * RAWH; idx += 256) {
        int r = idx / RAWH;
        int c = idx - r * RAWH;
        int gr = row0 - HALO + r;
        int gc = col0 - HALO + c;
        float a = 0.0f, b = 0.0f;
        if (gr >= 0 && gr < IMGH && gc >= 0 && gc < IMGW) {
            a = p1[gr * IMGW + gc];
            b = p2[gr * IMGW + gc];
            a = fminf(fmaxf(a, 0.0f), 1.0f);
            b = fminf(fmaxf(b, 0.0f), 1.0f);
        }
        s_ab[r * RS + c] = make_float2(a, b);
    }
    __syncthreads();

    // ---- Horizontal pass: group = 1 row x 8 output cols (74*4 = 296 groups) ----
    for (int g = tid; g < RAWV * 4; g += 256) {
        int r = g >> 2;
        int c0 = (g & 3) << 3;
        const float2* row = s_ab + r * RS + c0;

        float m1[8], m2[8], q11[8], q22[8], q12[8];
        #pragma unroll
        for (int j = 0; j < 8; j++) { m1[j]=0.f; m2[j]=0.f; q11[j]=0.f; q22[j]=0.f; q12[j]=0.f; }

        #pragma unroll
        for (int k = 0; k < 18; k++) {
            float2 ab = row[k];
            float sqa = ab.x * ab.x;
            float sqb = ab.y * ab.y;
            float pq  = ab.x * ab.y;
            #pragma unroll
            for (int j = 0; j < 8; j++) {
                const int kk = k - j;
                if (kk >= 0 && kk < 11) {
                    m1[j]  = fmaf(W[kk], ab.x, m1[j]);
                    m2[j]  = fmaf(W[kk], ab.y, m2[j]);
                    q11[j] = fmaf(W[kk], sqa, q11[j]);
                    q22[j] = fmaf(W[kk], sqb, q22[j]);
                    q12[j] = fmaf(W[kk], pq,  q12[j]);
                }
            }
        }
        int o = r * HS + c0;
        #pragma unroll
        for (int j = 0; j < 8; j++) {
            s_hm[o + j] = make_float2(m1[j], m2[j]);
            s_hq[o + j] = make_float2(q11[j], q22[j]);
            s_h12[o + j] = q12[j];
        }
    }
    __syncthreads();

    // ---- Vertical pass + SSIM: each thread = 1 col x 8 output rows ----
    float acc = 0.0f;
    {
        const int c = tid & 31;
        const int r0 = (tid >> 5) << 3;   // 0..56
        float vm1[8], vm2[8], e11[8], e22[8], e12[8];
        #pragma unroll
        for (int j = 0; j < 8; j++) { vm1[j]=0.f; vm2[j]=0.f; e11[j]=0.f; e22[j]=0.f; e12[j]=0.f; }

        #pragma unroll
        for (int k = 0; k < 18; k++) {
            int rr = (r0 + k) * HS + c;
            float2 hm = s_hm[rr];
            float2 hq = s_hq[rr];
            float h12 = s_h12[rr];
            #pragma unroll
            for (int j = 0; j < 8; j++) {
                const int kk = k - j;
                if (kk >= 0 && kk < 11) {
                    vm1[j] = fmaf(W[kk], hm.x, vm1[j]);
                    vm2[j] = fmaf(W[kk], hm.y, vm2[j]);
                    e11[j] = fmaf(W[kk], hq.x, e11[j]);
                    e22[j] = fmaf(W[kk], hq.y, e22[j]);
                    e12[j] = fmaf(W[kk], h12, e12[j]);
                }
            }
        }
        const float C1 = 1e-4f;   // 0.01^2
        const float C2 = 9e-4f;   // 0.03^2
        #pragma unroll
        for (int j = 0; j < 8; j++) {
            float mu1 = vm1[j], mu2 = vm2[j];
            float mu1s = mu1 * mu1;
            float mu2s = mu2 * mu2;
            float mu12 = mu1 * mu2;
            float sig1  = e11[j] - mu1s;
            float sig2  = e22[j] - mu2s;
            float sig12 = e12[j] - mu12;
            float num = (2.0f * mu12 + C1) * (2.0f * sig12 + C2);
            float den = (mu1s + mu2s + C1) * (sig1 + sig2 + C2);
            acc += __fdividef(num, den);
        }
    }

    // ---- Block reduction -> per-block partial ----
    #pragma unroll
    for (int o = 16; o > 0; o >>= 1)
        acc += __shfl_xor_sync(0xffffffffu, acc, o);
    if ((tid & 31) == 0) wsum[tid >> 5] = acc;
    __syncthreads();
    if (tid == 0) {
        float s = 0.0f;
        #pragma unroll
        for (int i = 0; i < 8; i++) s += wsum[i];
        int bid = blockIdx.x + 16 * (blockIdx.y + 8 * blockIdx.z);
        g_part[bid] = s;
    }
}

__global__ __launch_bounds__(1024) void ssim_final_kernel(float* out) {
    __shared__ double sh[32];
    const int tid = threadIdx.x;
    const float4* p4 = reinterpret_cast<const float4*>(g_part);  // 3072 float4
    float a0 = 0.f, a1 = 0.f, a2 = 0.f;
    {
        float4 v0 = p4[tid];
        float4 v1 = p4[tid + 1024];
        float4 v2 = p4[tid + 2048];
        a0 = (v0.x + v0.y) + (v0.z + v0.w);
        a1 = (v1.x + v1.y) + (v1.z + v1.w);
        a2 = (v2.x + v2.y) + (v2.z + v2.w);
    }
    double s = (double)a0 + (double)a1 + (double)a2;
    #pragma unroll
    for (int o = 16; o > 0; o >>= 1)
        s += __shfl_xor_sync(0xffffffffu, s, o);
    if ((tid & 31) == 0) sh[tid >> 5] = s;
    __syncthreads();
    if (tid == 0) {
        double t = 0.0;
        #pragma unroll
        for (int i = 0; i < 32; i++) t += sh[i];
        out[0] = (float)(1.0 - t * (1.0 / NPIX));
    }
}

extern "C" void kernel_launch(void* const* d_in, const int* in_sizes, int n_in,
                              void* d_out, int out_size) {
    const float* denoised = (const float*)d_in[0];
    const float* clean    = (const float*)d_in[1];
    float* out = (float*)d_out;

    cudaFuncSetAttribute(ssim_main_kernel,
                         cudaFuncAttributeMaxDynamicSharedMemorySize, SMEM_TOT);

    dim3 grid(IMGW / TW, IMGH / TH, 96);   // 16 x 8 x 96
    ssim_main_kernel<<<grid, 256, SMEM_TOT>>>(denoised, clean);
    ssim_final_kernel<<<1, 1024>>>(out);
}

// round 9
// speedup vs baseline: 1.0441x; 1.0441x over previous
#include <cuda_runtime.h>

// SSIM loss: 1 - mean(ssim_map(clip(denoised), clip(clean)))
// Separable 11x11 Gaussian (sigma=1.5), zero padding.
// (32,3,512,512) fp32 x2 -> scalar fp32.
// Single persistent kernel: tile conv + SSIM + last-block global reduce.

#define IMGW 512
#define IMGH 512
#define TW 32
#define TH 54
#define HALO 5
#define RAWV 64          // TH + 2*HALO
#define RAWH 42          // TW + 2*HALO
#define RS 46            // raw tile row stride (float2 units), even -> float4 reads
#define HS 32            // hsum row stride (elements)
#define HROWS 66         // padded hsum rows (reads reach r0+13 = 65)
#define NPIX 25165824.0  // 32*3*512*512
#define GX 16
#define GY 10            // ceil(512/54)
#define GZ 96
#define NBLK (GX*GY*GZ)  // 15360

__device__ float g_part[NBLK];
__device__ unsigned int g_count;   // zero-initialized; last block resets to 0

// dynamic smem layout (bytes):
#define OFF_AB   0
#define OFF_HM   (OFF_AB + RAWV*RS*8)        // float2[HROWS*HS]
#define OFF_HQ   (OFF_HM + HROWS*HS*8)       // float2[HROWS*HS]
#define OFF_H12  (OFF_HQ + HROWS*HS*8)       // float [HROWS*HS]
#define SMEM_TOT (OFF_H12 + HROWS*HS*4)

__global__ __launch_bounds__(512, 2) void ssim_main_kernel(
    const float* __restrict__ in1, const float* __restrict__ in2,
    float* __restrict__ out) {

    const float W[11] = {
        0.00102838f, 0.00759876f, 0.03600077f, 0.10936073f, 0.21300554f,
        0.26601172f,
        0.21300554f, 0.10936073f, 0.03600077f, 0.00759876f, 0.00102838f
    };

    extern __shared__ char smem[];
    float2* s_ab  = reinterpret_cast<float2*>(smem + OFF_AB);
    float2* s_hm  = reinterpret_cast<float2*>(smem + OFF_HM);
    float2* s_hq  = reinterpret_cast<float2*>(smem + OFF_HQ);
    float*  s_h12 = reinterpret_cast<float*>(smem + OFF_H12);
    __shared__ float wsum[16];
    __shared__ int s_islast;
    __shared__ double dsum[16];

    const int tid = threadIdx.x;
    const int plane = blockIdx.z;
    const int row0 = blockIdx.y * TH;
    const int col0 = blockIdx.x * TW;
    const float* p1 = in1 + (size_t)plane * (IMGW * IMGH);
    const float* p2 = in2 + (size_t)plane * (IMGW * IMGH);

    // ---- Load + clip raw tile with halo (zero outside image) ----
    for (int idx = tid; idx < RAWV * RAWH; idx += 512) {
        int r = idx / RAWH;
        int c = idx - r * RAWH;
        int gr = row0 - HALO + r;
        int gc = col0 - HALO + c;
        float a = 0.0f, b = 0.0f;
        if (gr >= 0 && gr < IMGH && gc >= 0 && gc < IMGW) {
            a = p1[gr * IMGW + gc];
            b = p2[gr * IMGW + gc];
            a = fminf(fmaxf(a, 0.0f), 1.0f);
            b = fminf(fmaxf(b, 0.0f), 1.0f);
        }
        s_ab[r * RS + c] = make_float2(a, b);
    }
    __syncthreads();

    // ---- Horizontal pass: exactly 1 task/thread: row r, 4 output cols ----
    {
        const int r  = tid >> 3;          // 0..63
        const int c0 = (tid & 7) << 2;    // 0,4,...,28
        const float4* rowq = reinterpret_cast<const float4*>(s_ab + r * RS + c0);

        float2 px[14];
        #pragma unroll
        for (int q = 0; q < 7; q++) {
            float4 v = rowq[q];
            px[2*q]   = make_float2(v.x, v.y);
            px[2*q+1] = make_float2(v.z, v.w);
        }

        float m1[4]  = {0.f,0.f,0.f,0.f};
        float m2[4]  = {0.f,0.f,0.f,0.f};
        float q11[4] = {0.f,0.f,0.f,0.f};
        float q22[4] = {0.f,0.f,0.f,0.f};
        float q12[4] = {0.f,0.f,0.f,0.f};

        #pragma unroll
        for (int k = 0; k < 14; k++) {
            float2 ab = px[k];
            float sqa = ab.x * ab.x;
            float sqb = ab.y * ab.y;
            float pq  = ab.x * ab.y;
            #pragma unroll
            for (int j = 0; j < 4; j++) {
                const int kk = k - j;
                if (kk >= 0 && kk < 11) {
                    m1[j]  = fmaf(W[kk], ab.x, m1[j]);
                    m2[j]  = fmaf(W[kk], ab.y, m2[j]);
                    q11[j] = fmaf(W[kk], sqa, q11[j]);
                    q22[j] = fmaf(W[kk], sqb, q22[j]);
                    q12[j] = fmaf(W[kk], pq,  q12[j]);
                }
            }
        }
        int o = r * HS + c0;
        #pragma unroll
        for (int j = 0; j < 4; j++) {
            s_hm[o + j] = make_float2(m1[j], m2[j]);
            s_hq[o + j] = make_float2(q11[j], q22[j]);
            s_h12[o + j] = q12[j];
        }
    }
    __syncthreads();

    // ---- Vertical pass + SSIM: thread = 1 col x 4 output rows ----
    float acc = 0.0f;
    {
        const int c  = tid & 31;
        const int r0 = (tid >> 5) << 2;    // 0..60 (r0 >= 54 -> idle)
        if (r0 < TH) {
            float vm1[4] = {0.f,0.f,0.f,0.f}, vm2[4] = {0.f,0.f,0.f,0.f};
            float e11[4] = {0.f,0.f,0.f,0.f}, e22[4] = {0.f,0.f,0.f,0.f};
            float e12[4] = {0.f,0.f,0.f,0.f};

            #pragma unroll
            for (int k = 0; k < 14; k++) {
                int rr = (r0 + k) * HS + c;
                float2 hm = s_hm[rr];
                float2 hq = s_hq[rr];
                float h12 = s_h12[rr];
                #pragma unroll
                for (int j = 0; j < 4; j++) {
                    const int kk = k - j;
                    if (kk >= 0 && kk < 11) {
                        vm1[j] = fmaf(W[kk], hm.x, vm1[j]);
                        vm2[j] = fmaf(W[kk], hm.y, vm2[j]);
                        e11[j] = fmaf(W[kk], hq.x, e11[j]);
                        e22[j] = fmaf(W[kk], hq.y, e22[j]);
                        e12[j] = fmaf(W[kk], h12, e12[j]);
                    }
                }
            }
            const float C1 = 1e-4f;   // 0.01^2
            const float C2 = 9e-4f;   // 0.03^2
            #pragma unroll
            for (int j = 0; j < 4; j++) {
                if (r0 + j < TH && row0 + r0 + j < IMGH) {
                    float mu1 = vm1[j], mu2 = vm2[j];
                    float mu1s = mu1 * mu1;
                    float mu2s = mu2 * mu2;
                    float mu12 = mu1 * mu2;
                    float sig1  = e11[j] - mu1s;
                    float sig2  = e22[j] - mu2s;
                    float sig12 = e12[j] - mu12;
                    float num = (2.0f * mu12 + C1) * (2.0f * sig12 + C2);
                    float den = (mu1s + mu2s + C1) * (sig1 + sig2 + C2);
                    acc += __fdividef(num, den);
                }
            }
        }
    }

    // ---- Block reduction -> per-block partial + last-block final reduce ----
    #pragma unroll
    for (int o = 16; o > 0; o >>= 1)
        acc += __shfl_xor_sync(0xffffffffu, acc, o);
    if ((tid & 31) == 0) wsum[tid >> 5] = acc;
    __syncthreads();
    if (tid == 0) {
        float s = 0.0f;
        #pragma unroll
        for (int i = 0; i < 16; i++) s += wsum[i];
        int bid = blockIdx.x + GX * (blockIdx.y + GY * blockIdx.z);
        g_part[bid] = s;
        __threadfence();
        unsigned int old = atomicAdd(&g_count, 1u);
        s_islast = (old == NBLK - 1) ? 1 : 0;
    }
    __syncthreads();

    if (s_islast) {
        __threadfence();
        const volatile float* vp = g_part;
        double d = 0.0;
        for (int i = tid; i < NBLK; i += 512) d += (double)vp[i];
        #pragma unroll
        for (int o = 16; o > 0; o >>= 1)
            d += __shfl_xor_sync(0xffffffffu, d, o);
        if ((tid & 31) == 0) dsum[tid >> 5] = d;
        __syncthreads();
        if (tid == 0) {
            double t = 0.0;
            #pragma unroll
            for (int i = 0; i < 16; i++) t += dsum[i];
            out[0] = (float)(1.0 - t * (1.0 / NPIX));
            g_count = 0;   // reset for next (graph-replayed) run
        }
    }
}

extern "C" void kernel_launch(void* const* d_in, const int* in_sizes, int n_in,
                              void* d_out, int out_size) {
    const float* denoised = (const float*)d_in[0];
    const float* clean    = (const float*)d_in[1];
    float* out = (float*)d_out;

    cudaFuncSetAttribute(ssim_main_kernel,
                         cudaFuncAttributeMaxDynamicSharedMemorySize, SMEM_TOT);

    dim3 grid(GX, GY, GZ);   // 16 x 10 x 96
    ssim_main_kernel<<<grid, 512, SMEM_TOT>>>(denoised, clean, out);
}

// round 10
// speedup vs baseline: 1.2249x; 1.1731x over previous
#include <cuda_runtime.h>

// SSIM loss: 1 - mean(ssim_map(clip(denoised), clip(clean)))
// Separable 11x11 Gaussian (sigma=1.5), zero padding.
// (32,3,512,512) fp32 x2 -> scalar fp32.
// One kernel: tile conv + SSIM + last-block reduce. 640 thr, TH=64, 2 blk/SM.

#define IMGW 512
#define IMGH 512
#define TW 32
#define TH 64
#define HALO 5
#define RAWV 74          // TH + 2*HALO
#define RAWH 42          // TW + 2*HALO
#define RS 44            // raw tile row stride (float2 units)
#define HS 33            // hsum row stride (conflict-free writes)
#define NPIX 25165824.0  // 32*3*512*512
#define GX 16
#define GY 8
#define GZ 96
#define NBLK (GX*GY*GZ)  // 12288
#define NTHR 640

__device__ float g_part[NBLK];
__device__ unsigned int g_count;   // zero-init; last block resets to 0

// dynamic smem layout (bytes):
#define OFF_AB   0
#define OFF_HM   (OFF_AB + RAWV*RS*8)        // float2[RAWV*HS]
#define OFF_HQ   (OFF_HM + RAWV*HS*8)        // float2[RAWV*HS]
#define OFF_H12  (OFF_HQ + RAWV*HS*8)        // float [RAWV*HS]
#define SMEM_TOT (OFF_H12 + RAWV*HS*4)       // 74888 B

__global__ __launch_bounds__(NTHR, 2) void ssim_main_kernel(
    const float* __restrict__ in1, const float* __restrict__ in2,
    float* __restrict__ out) {

    const float W[11] = {
        0.00102838f, 0.00759876f, 0.03600077f, 0.10936073f, 0.21300554f,
        0.26601172f,
        0.21300554f, 0.10936073f, 0.03600077f, 0.00759876f, 0.00102838f
    };

    extern __shared__ char smem[];
    float2* s_ab  = reinterpret_cast<float2*>(smem + OFF_AB);
    float2* s_hm  = reinterpret_cast<float2*>(smem + OFF_HM);
    float2* s_hq  = reinterpret_cast<float2*>(smem + OFF_HQ);
    float*  s_h12 = reinterpret_cast<float*>(smem + OFF_H12);
    __shared__ float wsum[20];
    __shared__ int s_islast;
    __shared__ double dsum[20];

    const int tid = threadIdx.x;
    const int plane = blockIdx.z;
    const int row0 = blockIdx.y * TH;
    const int col0 = blockIdx.x * TW;
    const float* p1 = in1 + (size_t)plane * (IMGW * IMGH);
    const float* p2 = in2 + (size_t)plane * (IMGW * IMGH);

    // ---- Load + clip raw tile with halo (zero outside image) ----
    for (int idx = tid; idx < RAWV * RAWH; idx += NTHR) {
        int r = idx / RAWH;
        int c = idx - r * RAWH;
        int gr = row0 - HALO + r;
        int gc = col0 - HALO + c;
        float a = 0.0f, b = 0.0f;
        if (gr >= 0 && gr < IMGH && gc >= 0 && gc < IMGW) {
            a = p1[gr * IMGW + gc];
            b = p2[gr * IMGW + gc];
            a = fminf(fmaxf(a, 0.0f), 1.0f);
            b = fminf(fmaxf(b, 0.0f), 1.0f);
        }
        s_ab[r * RS + c] = make_float2(a, b);
    }
    __syncthreads();

    // ---- Horizontal pass: 592 tasks, one per thread (single span) ----
    if (tid < RAWV * 8) {
        const int r  = tid >> 3;          // 0..73
        const int c0 = (tid & 7) << 2;    // 0,4,...,28
        const float2* row = s_ab + r * RS + c0;

        float m1[4]  = {0.f,0.f,0.f,0.f};
        float m2[4]  = {0.f,0.f,0.f,0.f};
        float q11[4] = {0.f,0.f,0.f,0.f};
        float q22[4] = {0.f,0.f,0.f,0.f};
        float q12[4] = {0.f,0.f,0.f,0.f};

        #pragma unroll
        for (int k = 0; k < 14; k++) {
            float2 ab = row[k];
            float sqa = ab.x * ab.x;
            float sqb = ab.y * ab.y;
            float pq  = ab.x * ab.y;
            #pragma unroll
            for (int j = 0; j < 4; j++) {
                const int kk = k - j;
                if (kk >= 0 && kk < 11) {
                    m1[j]  = fmaf(W[kk], ab.x, m1[j]);
                    m2[j]  = fmaf(W[kk], ab.y, m2[j]);
                    q11[j] = fmaf(W[kk], sqa, q11[j]);
                    q22[j] = fmaf(W[kk], sqb, q22[j]);
                    q12[j] = fmaf(W[kk], pq,  q12[j]);
                }
            }
        }
        int o = r * HS + c0;
        #pragma unroll
        for (int j = 0; j < 4; j++) {
            s_hm[o + j] = make_float2(m1[j], m2[j]);
            s_hq[o + j] = make_float2(q11[j], q22[j]);
            s_h12[o + j] = q12[j];
        }
    }
    __syncthreads();

    // ---- Vertical pass + SSIM: 512 threads, 1 col x 4 output rows each ----
    float acc = 0.0f;
    if (tid < 512) {
        const int c  = tid & 31;
        const int r0 = (tid >> 5) << 2;    // 0..60
        float vm1[4] = {0.f,0.f,0.f,0.f}, vm2[4] = {0.f,0.f,0.f,0.f};
        float e11[4] = {0.f,0.f,0.f,0.f}, e22[4] = {0.f,0.f,0.f,0.f};
        float e12[4] = {0.f,0.f,0.f,0.f};

        #pragma unroll
        for (int k = 0; k < 14; k++) {
            int rr = (r0 + k) * HS + c;
            float2 hm = s_hm[rr];
            float2 hq = s_hq[rr];
            float h12 = s_h12[rr];
            #pragma unroll
            for (int j = 0; j < 4; j++) {
                const int kk = k - j;
                if (kk >= 0 && kk < 11) {
                    vm1[j] = fmaf(W[kk], hm.x, vm1[j]);
                    vm2[j] = fmaf(W[kk], hm.y, vm2[j]);
                    e11[j] = fmaf(W[kk], hq.x, e11[j]);
                    e22[j] = fmaf(W[kk], hq.y, e22[j]);
                    e12[j] = fmaf(W[kk], h12, e12[j]);
                }
            }
        }
        const float C1 = 1e-4f;   // 0.01^2
        const float C2 = 9e-4f;   // 0.03^2
        #pragma unroll
        for (int j = 0; j < 4; j++) {
            float mu1 = vm1[j], mu2 = vm2[j];
            float mu1s = mu1 * mu1;
            float mu2s = mu2 * mu2;
            float mu12 = mu1 * mu2;
            float sig1  = e11[j] - mu1s;
            float sig2  = e22[j] - mu2s;
            float sig12 = e12[j] - mu12;
            float num = (2.0f * mu12 + C1) * (2.0f * sig12 + C2);
            float den = (mu1s + mu2s + C1) * (sig1 + sig2 + C2);
            acc += __fdividef(num, den);
        }
    }

    // ---- Block reduction -> per-block partial + last-block final reduce ----
    #pragma unroll
    for (int o = 16; o > 0; o >>= 1)
        acc += __shfl_xor_sync(0xffffffffu, acc, o);
    if ((tid & 31) == 0) wsum[tid >> 5] = acc;
    __syncthreads();
    if (tid == 0) {
        float s = 0.0f;
        #pragma unroll
        for (int i = 0; i < 20; i++) s += wsum[i];
        int bid = blockIdx.x + GX * (blockIdx.y + GY * blockIdx.z);
        g_part[bid] = s;
        __threadfence();
        unsigned int old = atomicAdd(&g_count, 1u);
        s_islast = (old == NBLK - 1) ? 1 : 0;
    }
    __syncthreads();

    if (s_islast) {
        __threadfence();
        const volatile float* vp = g_part;
        double d = 0.0;
        for (int i = tid; i < NBLK; i += NTHR) d += (double)vp[i];
        #pragma unroll
        for (int o = 16; o > 0; o >>= 1)
            d += __shfl_xor_sync(0xffffffffu, d, o);
        if ((tid & 31) == 0) dsum[tid >> 5] = d;
        __syncthreads();
        if (tid == 0) {
            double t = 0.0;
            #pragma unroll
            for (int i = 0; i < 20; i++) t += dsum[i];
            out[0] = (float)(1.0 - t * (1.0 / NPIX));
            g_count = 0;   // reset for next graph replay
        }
    }
}

extern "C" void kernel_launch(void* const* d_in, const int* in_sizes, int n_in,
                              void* d_out, int out_size) {
    const float* denoised = (const float*)d_in[0];
    const float* clean    = (const float*)d_in[1];
    float* out = (float*)d_out;

    cudaFuncSetAttribute(ssim_main_kernel,
                         cudaFuncAttributeMaxDynamicSharedMemorySize, SMEM_TOT);

    dim3 grid(GX, GY, GZ);   // 16 x 8 x 96
    ssim_main_kernel<<<grid, NTHR, SMEM_TOT>>>(denoised, clean, out);
}